// round 10
// baseline (speedup 1.0000x reference)
#include <cuda_runtime.h>
#include <math.h>

#define NB 8
#define NJ 17
#define NV 64
#define NPAIR (NB * NJ)             // 136
#define VOX (NV * NV * NV)          // 262144 elems = 1 MiB per pair
#define SPLIT 16
#define NBLOCKS (NPAIR * SPLIT)     // 2176
#define THREADS 256
#define CHUNK (VOX / SPLIT)         // 16384 elements per block
#define ITERS (CHUNK / 4 / THREADS) // 16 float4 per thread

__device__ float        g_pairsum[NPAIR];   // red.add target; reset by last block
__device__ float        g_picked[NPAIR];    // plain store by the matching block
__device__ unsigned int g_done = 0;         // reset by last block each launch

__device__ __forceinline__ int grid_idx(float l, float c) {
    float norm = (l - c) * (1.0f / 1000.0f);        // box_range = 1000
    int idx = (int)floorf((norm + 1.0f) * 0.5f * (float)(NV - 1));
    idx = idx < 0 ? 0 : (idx > NV - 1 ? NV - 1 : idx);
    return idx;
}

__global__ __launch_bounds__(THREADS)
void vol_ce_loss_kernel(const float* __restrict__ vol,
                        const float* __restrict__ label,
                        const float* __restrict__ center,
                        float* __restrict__ out) {
    const int blk  = blockIdx.x;
    const int pair = blk / SPLIT;
    const int part = blk % SPLIT;
    const int t    = threadIdx.x;

    // ---- streaming sum-of-exp (proven shape: plain unrolled __ldg loop) ----
    const float4* p = reinterpret_cast<const float4*>(
        vol + (size_t)pair * VOX + (size_t)part * CHUNK) + t;

    float s0 = 0.0f, s1 = 0.0f;
#pragma unroll
    for (int i = 0; i < ITERS; ++i) {
        float4 v = __ldg(p + i * THREADS);
        s0 += __expf(v.x) + __expf(v.y);
        s1 += __expf(v.z) + __expf(v.w);
    }
    float s = s0 + s1;

#pragma unroll
    for (int off = 16; off > 0; off >>= 1)
        s += __shfl_down_sync(0xFFFFFFFFu, s, off);

    __shared__ float sh[THREADS / 32];
    const int lane = t & 31;
    const int wid  = t >> 5;
    if (lane == 0) sh[wid] = s;
    __syncthreads();

    // ---- cheap epilogue: REDG + pick + release fence + completion counter ----
    __shared__ unsigned int amLast;
    if (t == 0) {
        float v = 0.0f;
#pragma unroll
        for (int k = 0; k < THREADS / 32; ++k) v += sh[k];
        atomicAdd(&g_pairsum[pair], v);   // result unused -> REDG, no return stall

        const int b = pair / NJ;
        const float cx = __ldg(center + b * 3 + 0);
        const float cy = __ldg(center + b * 3 + 1);
        const float cz = __ldg(center + b * 3 + 2);
        const float lx = __ldg(label + pair * 3 + 0);
        const float ly = __ldg(label + pair * 3 + 1);
        const float lz = __ldg(label + pair * 3 + 2);
        const int ix = grid_idx(lx, cx);
        const int iy = grid_idx(ly, cy);
        const int iz = grid_idx(lz, cz);
        const int flat = (ix * NV + iy) * NV + iz;
        if (flat >= part * CHUNK && flat < (part + 1) * CHUNK) {
            g_picked[pair] = __ldg(vol + (size_t)pair * VOX + flat);  // L1/L2 hot
        }

        __threadfence();  // release: REDG + picked visible before counter bump
        unsigned int prev = atomicAdd(&g_done, 1u);
        amLast = (prev == NBLOCKS - 1) ? 1u : 0u;
    }
    __syncthreads();      // block waits only on thread0's counter round trip

    if (!amLast) return;

    // ---- last-arriving block: parallel finalize, all data L2-hot ----
    __threadfence();      // acquire side of the counter handshake
    __shared__ float shr[256];
    float term = 0.0f;
    if (t < NPAIR) {
        const float S = g_pairsum[t];
        const float x = g_picked[t];
        const float pprob = __expf(x) / S;
        term = -logf(pprob + 1e-6f) * (0.01f / (float)NPAIR);
        g_pairsum[t] = 0.0f;            // reset for next graph replay
    }
    shr[t] = term;
    __syncthreads();
#pragma unroll
    for (int sdist = 128; sdist > 0; sdist >>= 1) {
        if (t < sdist) shr[t] += shr[t + sdist];
        __syncthreads();
    }
    if (t == 0) {
        out[0] = shr[0];
        g_done = 0u;                    // reset for next graph replay
        __threadfence();
    }
}

extern "C" void kernel_launch(void* const* d_in, const int* in_sizes, int n_in,
                              void* d_out, int out_size) {
    const float* vol    = (const float*)d_in[0];
    const float* label  = (const float*)d_in[1];
    const float* center = (const float*)d_in[2];
    float* out = (float*)d_out;

    vol_ce_loss_kernel<<<NBLOCKS, THREADS>>>(vol, label, center, out);
}